// round 16
// baseline (speedup 1.0000x reference)
#include <cuda_runtime.h>
#include <cuda_bf16.h>
#include <math.h>
#include <stdint.h>

// ---------------- problem constants ----------------
#define MAXB     1024
#define DIM      128
#define NSLICE   36                 // key slices (grid.y)
#define NSLOTS   (NSLICE * 2)       // per-slice key-halves
#define PK       4                  // stored candidate depth per slot
#define K8       8                  // merge list depth
#define TOPK     5
#define RESC     16                 // rescored quad candidates per query
#define INV_T    10.0f
#define NKEYMAX  200704             // >= N, 64-aligned

// ---------------- device scratch ----------------
__device__ int    g_excl[MAXB];
__device__ float  g_qn[MAXB * DIM];                      // normalized queries fp32
__device__ float  g_pval[8 * NSLOTS * 128 * PK];
__device__ int    g_pidx[8 * NSLOTS * 128 * PK];
__device__ int8_t g_q8[MAXB * DIM];                      // int8 queries
__device__ int8_t g_k8[(size_t)NKEYMAX * DIM];           // int8 keys (25.7 MB)

// ---------------- PTX helpers ----------------
__device__ __forceinline__ uint32_t smem_u32(const void* p) {
    uint32_t a;
    asm("{ .reg .u64 t; cvta.to.shared.u64 t, %1; cvt.u32.u64 %0, t; }" : "=r"(a) : "l"(p));
    return a;
}
__device__ __forceinline__ void cp16(uint32_t s, const void* g) {
    asm volatile("cp.async.cg.shared.global [%0], [%1], 16;" :: "r"(s), "l"(g));
}
#define CP_COMMIT()  asm volatile("cp.async.commit_group;")
#define CP_WAIT(n)   asm volatile("cp.async.wait_group %0;" :: "n"(n))

#define LDSM4(r0, r1, r2, r3, addr)                                         \
    asm volatile("ldmatrix.sync.aligned.m8n8.x4.shared.b16 {%0,%1,%2,%3}, [%4];" \
                 : "=r"(r0), "=r"(r1), "=r"(r2), "=r"(r3) : "r"(addr))

// s8 x s8 -> s32 MMA, accumulate
#define MMAI(c, a, b0, b1)                                                  \
    asm volatile("mma.sync.aligned.m16n8k32.row.col.s32.s8.s8.s32 "         \
                 "{%0,%1,%2,%3},{%4,%5,%6,%7},{%8,%9},{%0,%1,%2,%3};"       \
                 : "+r"((c)[0]), "+r"((c)[1]), "+r"((c)[2]), "+r"((c)[3])   \
                 : "r"((a)[0]), "r"((a)[1]), "r"((a)[2]), "r"((a)[3]),      \
                   "r"(b0), "r"(b1))

// first-k MMA: D = A*B + 0
#define MMAI_Z(c, a, b0, b1, zr)                                            \
    asm volatile("mma.sync.aligned.m16n8k32.row.col.s32.s8.s8.s32 "         \
                 "{%0,%1,%2,%3},{%4,%5,%6,%7},{%8,%9},{%10,%10,%10,%10};"   \
                 : "=r"((c)[0]), "=r"((c)[1]), "=r"((c)[2]), "=r"((c)[3])   \
                 : "r"((a)[0]), "r"((a)[1]), "r"((a)[2]), "r"((a)[3]),      \
                   "r"(b0), "r"(b1), "r"(zr))

// ---------------- branchless sorted-3 insert (int, IMNMX) ----------------
__device__ __forceinline__ void ins3i(int &a, int &b, int &c, int x) {
    int m;
    m = max(a, x); x = min(a, x); a = m;
    m = max(b, x); x = min(b, x); b = m;
    c = max(c, x);
}

// ---------------- top-8 (value,idx) helpers for the endgame merge ----------
__device__ __forceinline__ void t8_ins(float (&tv)[K8], int (&ti)[K8], float s, int idx) {
    tv[K8 - 1] = s; ti[K8 - 1] = idx;
    #pragma unroll
    for (int p = K8 - 1; p > 0; --p) {
        if (tv[p] > tv[p - 1]) {
            float fv = tv[p]; tv[p] = tv[p - 1]; tv[p - 1] = fv;
            int fi = ti[p]; ti[p] = ti[p - 1]; ti[p - 1] = fi;
        }
    }
}
__device__ __forceinline__ void t8_merge_xor(float (&tv)[K8], int (&ti)[K8], int off) {
    float pv[K8]; int pi[K8];
    #pragma unroll
    for (int r = 0; r < K8; ++r) {
        pv[r] = __shfl_xor_sync(0xffffffffu, tv[r], off);
        pi[r] = __shfl_xor_sync(0xffffffffu, ti[r], off);
    }
    #pragma unroll
    for (int r = 0; r < K8; ++r)
        if (pv[r] > tv[K8 - 1]) t8_ins(tv, ti, pv[r], pi[r]);
}

__device__ __forceinline__ uint32_t pack_s8x4(float a, float b, float c, float d) {
    int i0 = __float2int_rn(a * 127.f), i1 = __float2int_rn(b * 127.f);
    int i2 = __float2int_rn(c * 127.f), i3 = __float2int_rn(d * 127.f);
    return (uint32_t)(i0 & 255) | ((uint32_t)(i1 & 255) << 8) |
           ((uint32_t)(i2 & 255) << 16) | ((uint32_t)(i3 & 255) << 24);
}

// ---------------- kernel: fused query prep + exclude decode ----------------
__global__ void prep_all(const float* __restrict__ q, const void* __restrict__ ex,
                         int B) {
    if (blockIdx.x < (unsigned)(B / 8)) {
        int w = blockIdx.x * 8 + (threadIdx.x >> 5);
        int lane = threadIdx.x & 31;
        float4 v = *(const float4*)(q + (size_t)w * DIM + lane * 4);
        float ss = v.x * v.x + v.y * v.y + v.z * v.z + v.w * v.w;
        #pragma unroll
        for (int o = 16; o; o >>= 1) ss += __shfl_xor_sync(0xffffffffu, ss, o);
        float sc = 1.0f / fmaxf(sqrtf(ss), 1e-12f);
        float4 r = make_float4(v.x * sc, v.y * sc, v.z * sc, v.w * sc);
        size_t off = (size_t)w * DIM + lane * 4;
        *(float4*)(g_qn + off) = r;
        *(uint32_t*)(g_q8 + off) = pack_s8x4(r.x, r.y, r.z, r.w);
    } else {
        // exclude decode: int32 vs int64 sniff
        __shared__ int nz;
        int t = threadIdx.x;
        if (t == 0) nz = 0;
        __syncthreads();
        const int* e32 = (const int*)ex;
        for (int i = t; i < B / 2; i += blockDim.x)
            if (e32[2 * i + 1] != 0) atomicAdd(&nz, 1);
        __syncthreads();
        bool is64 = (nz == 0);
        for (int i = t; i < B; i += blockDim.x) {
            long long v = is64 ? ((const long long*)ex)[i] : (long long)e32[i];
            g_excl[i] = (int)v;
        }
    }
}

// ---------------- kernel: fp32 memory -> int8 ----------------
__global__ void quant_mem(const float* __restrict__ mem, int N) {
    int total4 = N * (DIM / 4);
    for (int i = blockIdx.x * blockDim.x + threadIdx.x; i < total4;
         i += gridDim.x * blockDim.x) {
        float4 v = ((const float4*)mem)[i];
        ((uint32_t*)g_k8)[i] = pack_s8x4(v.x, v.y, v.z, v.w);
    }
}

// ---------------- key tile loader: 64 keys x 128B int8, XOR-swizzled -------
__device__ __forceinline__ void load_ktile(uint32_t stage_u, int key0, bool valid, int tid) {
    if (valid) {
        #pragma unroll
        for (int c = tid; c < 512; c += 256) {
            int row = c >> 3, ch = c & 7;
            uint32_t off = (uint32_t)(row * 128 + (((ch ^ (row & 7))) << 4));
            cp16(stage_u + off, g_k8 + (size_t)(key0 + row) * DIM + ch * 16);
        }
    }
    CP_COMMIT();
}

// ---------------- main filter kernel: 256 threads, 2 CTAs/SM ---------------
__global__ void __launch_bounds__(256, 2)
sim_topk(int N, int Ntiles) {
    extern __shared__ __align__(16) char sm[];
    uint32_t smb = smem_u32(sm);
    uint32_t stage_u = (smb + 1023u) & ~1023u;

    int tid = threadIdx.x;
    int wid = tid >> 5;
    int lane = tid & 31;
    int wq = wid & 3;            // query-row group (32 rows)
    int kq = wid >> 2;           // key half (32 of the 64 tile keys)
    int qbase = blockIdx.x * 128;
    int slice = blockIdx.y;

    int TPC = (Ntiles + NSLICE - 1) / NSLICE;     // 87 (< 128, fits 7 bits)
    int t0 = slice * TPC;
    int T = min(TPC, Ntiles - t0); if (T < 0) T = 0;

    // prologue: 4 tiles in flight (6 stages total, 8KB each)
    load_ktile(stage_u,            (t0 + 0) * 64, 0 < T, tid);
    load_ktile(stage_u + 8192,     (t0 + 1) * 64, 1 < T, tid);
    load_ktile(stage_u + 2 * 8192, (t0 + 2) * 64, 2 < T, tid);
    load_ktile(stage_u + 3 * 8192, (t0 + 3) * 64, 3 < T, tid);

    // preload A fragments (int8 queries): 32 rows = 2 m16 blocks, 4 k-chunks
    int qr = qbase + wq * 32 + (lane >> 2);
    uint32_t ah[4][8];           // [kc][m*4 + j]
    #pragma unroll
    for (int kc = 0; kc < 4; ++kc) {
        int c = kc * 32 + (lane & 3) * 4;
        #pragma unroll
        for (int m = 0; m < 2; ++m) {
            const int8_t* qp = g_q8 + (size_t)(qr + m * 16) * DIM;
            ah[kc][m * 4 + 0] = *(const uint32_t*)(qp + c);
            ah[kc][m * 4 + 1] = *(const uint32_t*)(qp + 8 * DIM + c);
            ah[kc][m * 4 + 2] = *(const uint32_t*)(qp + c + 16);
            ah[kc][m * 4 + 3] = *(const uint32_t*)(qp + 8 * DIM + c + 16);
        }
    }

    // 4 per-lane top-3 QUAD lists (rows +0,+8,+16,+24), packed = (dot<<8)|meta
    int lv[4][3];
    #pragma unroll
    for (int l = 0; l < 4; ++l)
        lv[l][0] = lv[l][1] = lv[l][2] = (int)0x80000000;

    // LDSM lane mapping for int8 B fragments:
    // lanes 0-7: keys 0-7 chunk lo | 8-15: keys 0-7 chunk hi
    // lanes 16-23: keys 8-15 lo    | 24-31: keys 8-15 hi
    int key_local = (lane & 7) + ((lane >> 4) << 3);
    int chunkbit = (lane >> 3) & 1;
    int rowbase = kq * 32 + key_local;
    uint32_t off_h[4];
    #pragma unroll
    for (int kc = 0; kc < 4; ++kc)
        off_h[kc] = (uint32_t)(rowbase * 128 +
                    (((kc * 2 + chunkbit) ^ (lane & 7)) << 4));

    const int izero = 0;
    uint32_t st = stage_u;                        // stage of tile t
    uint32_t pf = stage_u + 4 * 8192;             // prefetch stage (t+4)
    const uint32_t stage_end = stage_u + 6 * 8192;

    for (int t = 0; t < T; ++t) {
        if ((t & 1) == 0) {
            CP_WAIT(2);                            // tiles t, t+1 resident
            __syncthreads();
            load_ktile(pf, (t0 + t + 4) * 64, (t + 4) < T, tid);
            pf += 8192; if (pf >= stage_end) pf = stage_u;
            load_ktile(pf, (t0 + t + 5) * 64, (t + 5) < T, tid);
            pf += 8192; if (pf >= stage_end) pf = stage_u;
        }

        #pragma unroll
        for (int nbp = 0; nbp < 2; ++nbp) {
            int acc[2][2][4];                // [m][n][j]
            #pragma unroll
            for (int kc = 0; kc < 4; ++kc) {
                uint32_t bh0, bh1, bh2, bh3;
                LDSM4(bh0, bh1, bh2, bh3, st + off_h[kc] + nbp * 2048);
                if (kc == 0) {
                    MMAI_Z(acc[0][0], (&ah[kc][0]), bh0, bh1, izero);
                    MMAI_Z(acc[1][0], (&ah[kc][4]), bh0, bh1, izero);
                    MMAI_Z(acc[0][1], (&ah[kc][0]), bh2, bh3, izero);
                    MMAI_Z(acc[1][1], (&ah[kc][4]), bh2, bh3, izero);
                } else {
                    MMAI(acc[0][0], (&ah[kc][0]), bh0, bh1);
                    MMAI(acc[1][0], (&ah[kc][4]), bh0, bh1);
                    MMAI(acc[0][1], (&ah[kc][0]), bh2, bh3);
                    MMAI(acc[1][1], (&ah[kc][4]), bh2, bh3);
                }
            }

            // ---- quad-max scan (int): quad = keys {p, p+1, p+8, p+9}
            int meta = (t << 1) | nbp;           // 8 bits
            #pragma unroll
            for (int m = 0; m < 2; ++m) {
                int qlo = max(max(acc[m][0][0], acc[m][0][1]),
                              max(acc[m][1][0], acc[m][1][1]));
                ins3i(lv[m * 2][0], lv[m * 2][1], lv[m * 2][2],
                      (qlo << 8) | meta);
                int qhi = max(max(acc[m][0][2], acc[m][0][3]),
                              max(acc[m][1][2], acc[m][1][3]));
                ins3i(lv[m * 2 + 1][0], lv[m * 2 + 1][1], lv[m * 2 + 1][2],
                      (qhi << 8) | meta);
            }
        }

        st += 8192; if (st >= stage_end) st = stage_u;
    }

    CP_WAIT(0);

    // ---- decode packed quad candidates, merge across the 4 lanes per row ---
    int cb = kq * 32 + (lane & 3) * 2;   // key base within 64-key tile
    #pragma unroll
    for (int l = 0; l < 4; ++l) {
        float tv[K8]; int ti[K8];
        #pragma unroll
        for (int r = 0; r < 3; ++r) {
            int u = lv[l][r];
            int meta = u & 0xFF;
            tv[r] = (float)u;                 // monotone in packed int
            // quad BASE index: members are base + {0, 1, 8, 9}
            ti[r] = (t0 + (meta >> 1)) * 64 + cb + (meta & 1) * 16;
        }
        #pragma unroll
        for (int r = 3; r < K8; ++r) { tv[r] = -INFINITY; ti[r] = -1; }

        t8_merge_xor(tv, ti, 1);
        t8_merge_xor(tv, ti, 2);

        if ((lane & 3) == 0) {
            int row = wq * 32 + (lane >> 2) + l * 8;
            size_t slotbase = (size_t)((blockIdx.x * NSLICE + slice) * 2 + kq) * 128;
            size_t b = (slotbase + row) * PK;
            #pragma unroll
            for (int r = 0; r < PK; ++r) { g_pval[b + r] = tv[r]; g_pidx[b + r] = ti[r]; }
        }
    }
}

// ---------------- merge + exact member rescore + softmax/gather/normalize ---
__global__ void merge_out(const float* __restrict__ mem, float* __restrict__ out,
                          int N, int B) {
    int q = (blockIdx.x * blockDim.x + threadIdx.x) >> 5;
    int lane = threadIdx.x & 31;
    if (q >= B) return;
    int qtile = q >> 7, ql = q & 127;
    int exq = g_excl[q];

    // ---- phase 1: approx top-RESC quads of 288 candidates (9 per lane).
    // Filter only garbage ids (>= N); exq handled per-member in rescore.
    float cv[9]; int ci[9];
    #pragma unroll
    for (int s = 0; s < 9; ++s) {
        int cidx = lane + 32 * s;                       // < 288 always
        int c = cidx >> 2, r = cidx & 3;
        size_t base = ((size_t)(qtile * NSLOTS + c) * 128 + ql) * PK + r;
        float v = g_pval[base]; int id = g_pidx[base];
        if ((unsigned)id >= (unsigned)N) v = -INFINITY;
        cv[s] = v; ci[s] = id;
    }

    int ridx[RESC];
    #pragma unroll
    for (int k = 0; k < RESC; ++k) {
        float bv = cv[0]; int bi = ci[0];
        #pragma unroll
        for (int s = 1; s < 9; ++s)
            if (cv[s] > bv || (cv[s] == bv && ci[s] < bi)) { bv = cv[s]; bi = ci[s]; }
        #pragma unroll
        for (int o = 16; o; o >>= 1) {
            float ov = __shfl_xor_sync(0xffffffffu, bv, o);
            int   oi = __shfl_xor_sync(0xffffffffu, bi, o);
            if (ov > bv || (ov == bv && oi < bi)) { bv = ov; bi = oi; }
        }
        ridx[k] = (bi < 0 || bi >= N) ? 0 : bi;   // safety clamp (quad base)
        #pragma unroll
        for (int s = 0; s < 9; ++s) if (ci[s] == bi) cv[s] = -INFINITY;
    }

    // ---- phase 2+3 fused: exact fp32 rescore of all 4 members of each quad,
    // maintaining a running exact top-5 (ties -> lower index first)
    float4 qv = *(const float4*)(g_qn + (size_t)q * DIM + lane * 4);
    float tv[TOPK]; int ti[TOPK];
    #pragma unroll
    for (int k = 0; k < TOPK; ++k) { tv[k] = -INFINITY; ti[k] = 0x7fffffff; }

    #pragma unroll
    for (int k = 0; k < RESC; ++k) {
        #pragma unroll
        for (int mb = 0; mb < 4; ++mb) {
            int id = ridx[k] + (mb & 1) + ((mb >> 1) << 3);   // +{0,1,8,9}
            float4 m4 = *(const float4*)(mem + (size_t)id * DIM + lane * 4);
            float d = qv.x * m4.x + qv.y * m4.y + qv.z * m4.z + qv.w * m4.w;
            #pragma unroll
            for (int o = 16; o; o >>= 1) d += __shfl_xor_sync(0xffffffffu, d, o);
            if (id >= N || id == exq) d = -INFINITY;
            if (d > tv[TOPK - 1] ||
                (d == tv[TOPK - 1] && id < ti[TOPK - 1])) {
                tv[TOPK - 1] = d; ti[TOPK - 1] = id;
                #pragma unroll
                for (int p = TOPK - 1; p > 0; --p) {
                    if (tv[p] > tv[p - 1] ||
                        (tv[p] == tv[p - 1] && ti[p] < ti[p - 1])) {
                        float fv = tv[p]; tv[p] = tv[p - 1]; tv[p - 1] = fv;
                        int fi = ti[p]; ti[p] = ti[p - 1]; ti[p - 1] = fi;
                    }
                }
            }
        }
    }

    // ---- softmax over exact top sims
    float e[TOPK], ssum = 0.f;
    #pragma unroll
    for (int k = 0; k < TOPK; ++k) { e[k] = expf((tv[k] - tv[0]) * INV_T); ssum += e[k]; }
    float w[TOPK];
    #pragma unroll
    for (int k = 0; k < TOPK; ++k) w[k] = e[k] / ssum;

    // ---- weighted gather + renormalize
    int d0 = lane * 4;
    float4 a = make_float4(0.f, 0.f, 0.f, 0.f);
    #pragma unroll
    for (int k = 0; k < TOPK; ++k) {
        float4 m4 = *(const float4*)(mem + (size_t)ti[k] * DIM + d0);
        a.x += w[k] * m4.x; a.y += w[k] * m4.y; a.z += w[k] * m4.z; a.w += w[k] * m4.w;
    }
    float ss = a.x * a.x + a.y * a.y + a.z * a.z + a.w * a.w;
    #pragma unroll
    for (int o = 16; o; o >>= 1) ss += __shfl_xor_sync(0xffffffffu, ss, o);
    float sc = 1.0f / fmaxf(sqrtf(ss), 1e-12f);
    float4 r4 = make_float4(a.x * sc, a.y * sc, a.z * sc, a.w * sc);
    *(float4*)(out + (size_t)q * DIM + d0) = r4;

    if (lane == 0) {
        out[(size_t)B * DIM + q] = 1.0f - tv[0];
        #pragma unroll
        for (int k = 0; k < TOPK; ++k)
            out[(size_t)B * DIM + B + (size_t)q * TOPK + k] = w[k];
    }
}

// ---------------- launch ----------------
extern "C" void kernel_launch(void* const* d_in, const int* in_sizes, int n_in,
                              void* d_out, int out_size) {
    const float* query  = (const float*)d_in[0];
    const float* memory = (const float*)d_in[1];
    const void*  excl   = d_in[3];
    int B = in_sizes[0] / DIM;              // 1024
    int N = in_sizes[1] / DIM;              // 200000 (divisible by 64)
    int Ntiles = (N + 63) / 64;             // 3125 tiles of 64 keys
    float* out = (float*)d_out;

    prep_all<<<B / 8 + 1, 256>>>(query, excl, B);
    quant_mem<<<2048, 256>>>(memory, N);

    const int SMEM = 6 * 8192 + 1024;       // 50,176 B per CTA (2 CTAs/SM)
    cudaFuncSetAttribute(sim_topk, cudaFuncAttributeMaxDynamicSharedMemorySize, SMEM);
    sim_topk<<<dim3(B / 128, NSLICE), 256, SMEM>>>(N, Ntiles);

    merge_out<<<(B * 32 + 255) / 256, 256>>>(memory, out, N, B);
}

// round 17
// speedup vs baseline: 2.5446x; 2.5446x over previous
#include <cuda_runtime.h>
#include <cuda_bf16.h>
#include <math.h>
#include <stdint.h>

// ---------------- problem constants ----------------
#define MAXB     1024
#define DIM      128
#define NSLICE   37                 // key slices (grid.y): 8*37=296 = 2 CTAs/SM
#define NSLOTS   (NSLICE * 2)       // per-slice key-halves (74)
#define PK       4                  // stored candidate depth per slot
#define K8       8                  // merge list depth
#define TOPK     5
#define RESC     10                 // rescored quad candidates per query
#define INV_T    10.0f
#define NPADMAX  (3128 * 64)

// ---------------- device scratch ----------------
__device__ int   g_excl[MAXB];
__device__ float g_qn[MAXB * DIM];                       // normalized queries fp32
__device__ float g_pval[8 * NSLOTS * 128 * PK];
__device__ int   g_pidx[8 * NSLOTS * 128 * PK];
__device__ __nv_bfloat16 g_qh[MAXB * DIM];
__device__ __nv_bfloat16 g_kh[(size_t)NPADMAX * DIM];    // 51.2 MB

// ---------------- PTX helpers ----------------
__device__ __forceinline__ uint32_t smem_u32(const void* p) {
    uint32_t a;
    asm("{ .reg .u64 t; cvta.to.shared.u64 t, %1; cvt.u32.u64 %0, t; }" : "=r"(a) : "l"(p));
    return a;
}
__device__ __forceinline__ void cp16(uint32_t s, const void* g) {
    asm volatile("cp.async.cg.shared.global [%0], [%1], 16;" :: "r"(s), "l"(g));
}
#define CP_COMMIT()  asm volatile("cp.async.commit_group;")
#define CP_WAIT(n)   asm volatile("cp.async.wait_group %0;" :: "n"(n))

#define LDSM4(r0, r1, r2, r3, addr)                                         \
    asm volatile("ldmatrix.sync.aligned.m8n8.x4.shared.b16 {%0,%1,%2,%3}, [%4];" \
                 : "=r"(r0), "=r"(r1), "=r"(r2), "=r"(r3) : "r"(addr))

#define MMA16816(c, a, b0, b1)                                              \
    asm volatile("mma.sync.aligned.m16n8k16.row.col.f32.bf16.bf16.f32 "     \
                 "{%0,%1,%2,%3},{%4,%5,%6,%7},{%8,%9},{%0,%1,%2,%3};"       \
                 : "+f"((c)[0]), "+f"((c)[1]), "+f"((c)[2]), "+f"((c)[3])   \
                 : "r"((a)[0]), "r"((a)[1]), "r"((a)[2]), "r"((a)[3]),      \
                   "r"(b0), "r"(b1))

// first-k MMA: D = A*B + 0 (separate zero C input; kills acc-init MOVs)
#define MMA16816_Z(c, a, b0, b1, zr)                                        \
    asm volatile("mma.sync.aligned.m16n8k16.row.col.f32.bf16.bf16.f32 "     \
                 "{%0,%1,%2,%3},{%4,%5,%6,%7},{%8,%9},{%10,%10,%10,%10};"   \
                 : "=f"((c)[0]), "=f"((c)[1]), "=f"((c)[2]), "=f"((c)[3])   \
                 : "r"((a)[0]), "r"((a)[1]), "r"((a)[2]), "r"((a)[3]),      \
                   "r"(b0), "r"(b1), "f"(zr))

// ---------------- branchless sorted-3 insert (5 FMNMX, no indices) --------
__device__ __forceinline__ void ins3(float &a, float &b, float &c, float x) {
    float m;
    m = fmaxf(a, x); x = fminf(a, x); a = m;
    m = fmaxf(b, x); x = fminf(b, x); b = m;
    c = fmaxf(c, x);
}

// ---------------- branchless sorted-5 insert (unsigned, 9 IMNMX) ----------
__device__ __forceinline__ void ins5u(uint32_t &a, uint32_t &b, uint32_t &c,
                                      uint32_t &d, uint32_t &e, uint32_t x) {
    uint32_t m;
    m = max(a, x); x = min(a, x); a = m;
    m = max(b, x); x = min(b, x); b = m;
    m = max(c, x); x = min(c, x); c = m;
    m = max(d, x); x = min(d, x); d = m;
    e = max(e, x);
}

// ---------------- top-8 (value,idx) helpers for the endgame merge ----------
__device__ __forceinline__ void t8_ins(float (&tv)[K8], int (&ti)[K8], float s, int idx) {
    tv[K8 - 1] = s; ti[K8 - 1] = idx;
    #pragma unroll
    for (int p = K8 - 1; p > 0; --p) {
        if (tv[p] > tv[p - 1]) {
            float fv = tv[p]; tv[p] = tv[p - 1]; tv[p - 1] = fv;
            int fi = ti[p]; ti[p] = ti[p - 1]; ti[p - 1] = fi;
        }
    }
}
__device__ __forceinline__ void t8_merge_xor(float (&tv)[K8], int (&ti)[K8], int off) {
    float pv[K8]; int pi[K8];
    #pragma unroll
    for (int r = 0; r < K8; ++r) {
        pv[r] = __shfl_xor_sync(0xffffffffu, tv[r], off);
        pi[r] = __shfl_xor_sync(0xffffffffu, ti[r], off);
    }
    #pragma unroll
    for (int r = 0; r < K8; ++r)
        if (pv[r] > tv[K8 - 1]) t8_ins(tv, ti, pv[r], pi[r]);
}

// ---------------- kernel: fused query prep + exclude decode ----------------
__global__ void prep_all(const float* __restrict__ q, const void* __restrict__ ex,
                         int B) {
    if (blockIdx.x < (unsigned)(B / 8)) {
        int w = blockIdx.x * 8 + (threadIdx.x >> 5);
        int lane = threadIdx.x & 31;
        float4 v = *(const float4*)(q + (size_t)w * DIM + lane * 4);
        float ss = v.x * v.x + v.y * v.y + v.z * v.z + v.w * v.w;
        #pragma unroll
        for (int o = 16; o; o >>= 1) ss += __shfl_xor_sync(0xffffffffu, ss, o);
        float sc = 1.0f / fmaxf(sqrtf(ss), 1e-12f);
        float4 r = make_float4(v.x * sc, v.y * sc, v.z * sc, v.w * sc);
        size_t off = (size_t)w * DIM + lane * 4;
        *(float4*)(g_qn + off) = r;
        __nv_bfloat162 h0 = __floats2bfloat162_rn(r.x, r.y);
        __nv_bfloat162 h1 = __floats2bfloat162_rn(r.z, r.w);
        *(uint2*)(g_qh + off) = make_uint2(*(uint32_t*)&h0, *(uint32_t*)&h1);
    } else {
        // exclude decode: int32 vs int64 sniff
        __shared__ int nz;
        int t = threadIdx.x;
        if (t == 0) nz = 0;
        __syncthreads();
        const int* e32 = (const int*)ex;
        for (int i = t; i < B / 2; i += blockDim.x)
            if (e32[2 * i + 1] != 0) atomicAdd(&nz, 1);
        __syncthreads();
        bool is64 = (nz == 0);
        for (int i = t; i < B; i += blockDim.x) {
            long long v = is64 ? ((const long long*)ex)[i] : (long long)e32[i];
            g_excl[i] = (int)v;
        }
    }
}

// ---------------- kernel: fp32 memory -> bf16 hi ----------------
__global__ void split_mem(const float* __restrict__ mem, int N, int NPAD) {
    int total4 = NPAD * (DIM / 4);
    for (int i = blockIdx.x * blockDim.x + threadIdx.x; i < total4;
         i += gridDim.x * blockDim.x) {
        int row = i >> 5;
        float4 v = make_float4(0.f, 0.f, 0.f, 0.f);
        if (row < N) v = ((const float4*)mem)[i];
        __nv_bfloat162 h0 = __floats2bfloat162_rn(v.x, v.y);
        __nv_bfloat162 h1 = __floats2bfloat162_rn(v.z, v.w);
        ((uint2*)g_kh)[i] = make_uint2(*(uint32_t*)&h0, *(uint32_t*)&h1);
    }
}

// ---------------- key tile loader: 64 keys x 256B, XOR-swizzled ------------
__device__ __forceinline__ void load_ktile(uint32_t stage_u, int key0, bool valid, int tid) {
    if (valid) {
        #pragma unroll
        for (int c = tid; c < 1024; c += 256) {
            int row = c >> 4, ch = c & 15;
            uint32_t off = (uint32_t)(row * 256 + (((ch ^ (row & 7))) << 4));
            cp16(stage_u + off, g_kh + (size_t)(key0 + row) * DIM + ch * 8);
        }
    }
    CP_COMMIT();
}

// ---------------- main filter kernel: 256 threads, 2 CTAs/SM ---------------
__global__ void __launch_bounds__(256, 2)
sim_topk(int N, int Ntiles) {
    extern __shared__ __align__(16) char sm[];
    uint32_t smb = smem_u32(sm);
    uint32_t stage_u = (smb + 1023u) & ~1023u;

    int tid = threadIdx.x;
    int wid = tid >> 5;
    int lane = tid & 31;
    int wq = wid & 3;            // query-row group (32 rows)
    int kq = wid >> 2;           // key half (32 of the 64 tile keys)
    int qbase = blockIdx.x * 128;
    int slice = blockIdx.y;

    int TPC = (Ntiles + NSLICE - 1) / NSLICE;     // 85 (< 128, fits 7 bits)
    int t0 = slice * TPC;
    int T = min(TPC, Ntiles - t0); if (T < 0) T = 0;

    // prologue: 4 tiles in flight (6 stages total)
    load_ktile(stage_u,             (t0 + 0) * 64, 0 < T, tid);
    load_ktile(stage_u + 16384,     (t0 + 1) * 64, 1 < T, tid);
    load_ktile(stage_u + 2 * 16384, (t0 + 2) * 64, 2 < T, tid);
    load_ktile(stage_u + 3 * 16384, (t0 + 3) * 64, 3 < T, tid);

    // preload A fragments: this warp's 32 query rows = 2 m16 blocks
    int qr = qbase + wq * 32 + (lane >> 2);
    uint32_t ah[8][8];           // [kc][m*4 + j]
    #pragma unroll
    for (int kc = 0; kc < 8; ++kc) {
        int c = kc * 16 + (lane & 3) * 2;
        #pragma unroll
        for (int m = 0; m < 2; ++m) {
            const __nv_bfloat16* qp = g_qh + (size_t)(qr + m * 16) * DIM;
            ah[kc][m * 4 + 0] = *(const uint32_t*)(qp + c);
            ah[kc][m * 4 + 1] = *(const uint32_t*)(qp + 8 * DIM + c);
            ah[kc][m * 4 + 2] = *(const uint32_t*)(qp + c + 8);
            ah[kc][m * 4 + 3] = *(const uint32_t*)(qp + 8 * DIM + c + 8);
        }
    }

    // 4 per-lane top-3 QUAD lists (rows +0,+8,+16,+24), meta in low 8 bits
    float lv[4][3];
    #pragma unroll
    for (int l = 0; l < 4; ++l)
        lv[l][0] = lv[l][1] = lv[l][2] = -3.0e38f;

    int r_   = lane & 7;
    int cbit = (lane >> 3) & 1;
    int kb256 = (kq << 13) + ((lane >> 4) * 8 + r_) * 256;

    // precompute swizzled LDSM offsets (constant across tiles)
    uint32_t off_h[8];
    #pragma unroll
    for (int kc = 0; kc < 8; ++kc)
        off_h[kc] = (uint32_t)kb256 + (uint32_t)(((kc * 2 + cbit) ^ r_) << 4);

    const float fzero = 0.0f;
    uint32_t st = stage_u;                        // stage of tile t
    uint32_t pf = stage_u + 4 * 16384;            // prefetch stage (t+4)
    const uint32_t stage_end = stage_u + 6 * 16384;

    for (int t = 0; t < T; ++t) {
        if ((t & 1) == 0) {
            CP_WAIT(2);                            // tiles t, t+1 resident
            __syncthreads();
            load_ktile(pf, (t0 + t + 4) * 64, (t + 4) < T, tid);
            pf += 16384; if (pf >= stage_end) pf = stage_u;
            load_ktile(pf, (t0 + t + 5) * 64, (t + 5) < T, tid);
            pf += 16384; if (pf >= stage_end) pf = stage_u;
        }

        #pragma unroll
        for (int nbp = 0; nbp < 2; ++nbp) {
            float acc[2][2][4];              // [m][n][j]
            #pragma unroll
            for (int kc = 0; kc < 8; ++kc) {
                uint32_t bh0, bh1, bh2, bh3;
                LDSM4(bh0, bh1, bh2, bh3, st + off_h[kc] + nbp * 4096);
                if (kc == 0) {
                    MMA16816_Z(acc[0][0], (&ah[kc][0]), bh0, bh1, fzero);
                    MMA16816_Z(acc[1][0], (&ah[kc][4]), bh0, bh1, fzero);
                    MMA16816_Z(acc[0][1], (&ah[kc][0]), bh2, bh3, fzero);
                    MMA16816_Z(acc[1][1], (&ah[kc][4]), bh2, bh3, fzero);
                } else {
                    MMA16816(acc[0][0], (&ah[kc][0]), bh0, bh1);
                    MMA16816(acc[1][0], (&ah[kc][4]), bh0, bh1);
                    MMA16816(acc[0][1], (&ah[kc][0]), bh2, bh3);
                    MMA16816(acc[1][1], (&ah[kc][4]), bh2, bh3);
                }
            }

            // ---- quad-max scan: 1 candidate per row per nbp
            // quad = keys {p, p+1, p+8, p+9}; members recovered by exact rescore
            uint32_t meta = ((uint32_t)t << 1) | (uint32_t)nbp;   // 8 bits
            #pragma unroll
            for (int m = 0; m < 2; ++m) {
                float qlo = fmaxf(fmaxf(acc[m][0][0], acc[m][0][1]),
                                  fmaxf(acc[m][1][0], acc[m][1][1]));
                uint32_t s = (__float_as_uint(qlo) & 0xFFFFFF00u) | meta;
                ins3(lv[m * 2][0], lv[m * 2][1], lv[m * 2][2], __uint_as_float(s));
                float qhi = fmaxf(fmaxf(acc[m][0][2], acc[m][0][3]),
                                  fmaxf(acc[m][1][2], acc[m][1][3]));
                s = (__float_as_uint(qhi) & 0xFFFFFF00u) | meta;
                ins3(lv[m * 2 + 1][0], lv[m * 2 + 1][1], lv[m * 2 + 1][2],
                     __uint_as_float(s));
            }
        }

        st += 16384; if (st >= stage_end) st = stage_u;
    }

    CP_WAIT(0);

    // ---- decode packed quad candidates, merge across the 4 lanes per row ---
    int cb = kq * 32 + (lane & 3) * 2;   // key base within 64-key tile
    #pragma unroll
    for (int l = 0; l < 4; ++l) {
        float tv[K8]; int ti[K8];
        #pragma unroll
        for (int r = 0; r < 3; ++r) {
            uint32_t u = __float_as_uint(lv[l][r]);
            tv[r] = lv[l][r];
            // quad BASE index: members are base + {0, 1, 8, 9}
            ti[r] = (t0 + (int)((u >> 1) & 0x7F)) * 64 + cb + (int)(u & 1) * 16;
        }
        #pragma unroll
        for (int r = 3; r < K8; ++r) { tv[r] = -INFINITY; ti[r] = -1; }

        t8_merge_xor(tv, ti, 1);
        t8_merge_xor(tv, ti, 2);

        if ((lane & 3) == 0) {
            int row = wq * 32 + (lane >> 2) + l * 8;
            size_t slotbase = (size_t)((blockIdx.x * NSLICE + slice) * 2 + kq) * 128;
            size_t b = (slotbase + row) * PK;
            #pragma unroll
            for (int r = 0; r < PK; ++r) { g_pval[b + r] = tv[r]; g_pidx[b + r] = ti[r]; }
        }
    }
}

// ---------------- merge + exact member rescore + softmax/gather/normalize ---
__global__ void merge_out(const float* __restrict__ mem, float* __restrict__ out,
                          int N, int B) {
    int q = (blockIdx.x * blockDim.x + threadIdx.x) >> 5;
    int lane = threadIdx.x & 31;
    if (q >= B) return;
    int qtile = q >> 7, ql = q & 127;
    int exq = g_excl[q];

    // ---- phase 1: approx top-RESC quads of 296 candidates (10 per lane).
    // Filter only garbage ids (>= N); exq handled per-member in rescore.
    const int NCAND = NSLOTS * PK;                      // 296
    float cv[10]; int ci[10];
    #pragma unroll
    for (int s = 0; s < 10; ++s) {
        int cidx = lane + 32 * s;
        if (cidx < NCAND) {
            int c = cidx >> 2, r = cidx & 3;
            size_t base = ((size_t)(qtile * NSLOTS + c) * 128 + ql) * PK + r;
            float v = g_pval[base]; int id = g_pidx[base];
            if ((unsigned)id >= (unsigned)N) v = -INFINITY;
            cv[s] = v; ci[s] = id;
        } else { cv[s] = -INFINITY; ci[s] = 0x7fffffff; }
    }

    int ridx[RESC];
    #pragma unroll
    for (int k = 0; k < RESC; ++k) {
        float bv = cv[0]; int bi = ci[0];
        #pragma unroll
        for (int s = 1; s < 10; ++s)
            if (cv[s] > bv || (cv[s] == bv && ci[s] < bi)) { bv = cv[s]; bi = ci[s]; }
        #pragma unroll
        for (int o = 16; o; o >>= 1) {
            float ov = __shfl_xor_sync(0xffffffffu, bv, o);
            int   oi = __shfl_xor_sync(0xffffffffu, bi, o);
            if (ov > bv || (ov == bv && oi < bi)) { bv = ov; bi = oi; }
        }
        ridx[k] = (bi < 0 || bi >= N) ? 0 : bi;   // safety clamp (quad base)
        #pragma unroll
        for (int s = 0; s < 10; ++s) if (ci[s] == bi) cv[s] = -INFINITY;
    }

    // ---- phase 2+3: exact fp32 rescore of all 40 members; branchless packed
    // top-5 (sort-monotone uint with member-id in low 6 bits)
    float4 qv = *(const float4*)(g_qn + (size_t)q * DIM + lane * 4);
    uint32_t b0 = 0, b1 = 0, b2 = 0, b3 = 0, b4 = 0;
    #pragma unroll
    for (int k = 0; k < RESC; ++k) {
        #pragma unroll
        for (int mb = 0; mb < 4; ++mb) {
            int id = ridx[k] + (mb & 1) + ((mb >> 1) << 3);   // +{0,1,8,9}
            float4 m4 = *(const float4*)(mem + (size_t)id * DIM + lane * 4);
            float d = qv.x * m4.x + qv.y * m4.y + qv.z * m4.z + qv.w * m4.w;
            #pragma unroll
            for (int o = 16; o; o >>= 1) d += __shfl_xor_sync(0xffffffffu, d, o);
            if (id >= N || id == exq) d = -INFINITY;
            int ib = __float_as_int(d);
            uint32_t u = (uint32_t)(ib ^ ((ib >> 31) | 0x80000000));
            u = (u & ~63u) | (uint32_t)(k * 4 + mb);
            ins5u(b0, b1, b2, b3, b4, u);
        }
    }

    // decode top-5 packed -> (value, index)
    uint32_t bl[TOPK] = { b0, b1, b2, b3, b4 };
    float tv[TOPK]; int ti[TOPK];
    #pragma unroll
    for (int k = 0; k < TOPK; ++k) {
        uint32_t u = bl[k];
        int j = (int)(u & 63u);
        int mk = j >> 2, mb = j & 3;
        ti[k] = ridx[mk] + (mb & 1) + ((mb >> 1) << 3);
        uint32_t uv = u & ~63u;
        int ib = (uv & 0x80000000u) ? (int)(uv ^ 0x80000000u) : (int)(~uv);
        tv[k] = __int_as_float(ib);
    }

    // ---- softmax over exact top sims
    float e[TOPK], ssum = 0.f;
    #pragma unroll
    for (int k = 0; k < TOPK; ++k) { e[k] = expf((tv[k] - tv[0]) * INV_T); ssum += e[k]; }
    float w[TOPK];
    #pragma unroll
    for (int k = 0; k < TOPK; ++k) w[k] = e[k] / ssum;

    // ---- weighted gather + renormalize
    int d0 = lane * 4;
    float4 a = make_float4(0.f, 0.f, 0.f, 0.f);
    #pragma unroll
    for (int k = 0; k < TOPK; ++k) {
        float4 m4 = *(const float4*)(mem + (size_t)ti[k] * DIM + d0);
        a.x += w[k] * m4.x; a.y += w[k] * m4.y; a.z += w[k] * m4.z; a.w += w[k] * m4.w;
    }
    float ss = a.x * a.x + a.y * a.y + a.z * a.z + a.w * a.w;
    #pragma unroll
    for (int o = 16; o; o >>= 1) ss += __shfl_xor_sync(0xffffffffu, ss, o);
    float sc = 1.0f / fmaxf(sqrtf(ss), 1e-12f);
    float4 r4 = make_float4(a.x * sc, a.y * sc, a.z * sc, a.w * sc);
    *(float4*)(out + (size_t)q * DIM + d0) = r4;

    if (lane == 0) {
        out[(size_t)B * DIM + q] = 1.0f - tv[0];
        #pragma unroll
        for (int k = 0; k < TOPK; ++k)
            out[(size_t)B * DIM + B + (size_t)q * TOPK + k] = w[k];
    }
}

// ---------------- launch ----------------
extern "C" void kernel_launch(void* const* d_in, const int* in_sizes, int n_in,
                              void* d_out, int out_size) {
    const float* query  = (const float*)d_in[0];
    const float* memory = (const float*)d_in[1];
    const void*  excl   = d_in[3];
    int B = in_sizes[0] / DIM;              // 1024
    int N = in_sizes[1] / DIM;              // 200000
    int Ntiles = (N + 63) / 64;             // 3125 tiles of 64 keys
    int NPAD = Ntiles * 64;
    float* out = (float*)d_out;

    prep_all<<<B / 8 + 1, 256>>>(query, excl, B);
    split_mem<<<2048, 256>>>(memory, N, NPAD);

    const int SMEM = 6 * 16384 + 1024;      // 99,328 B per CTA (2 CTAs/SM)
    cudaFuncSetAttribute(sim_topk, cudaFuncAttributeMaxDynamicSharedMemorySize, SMEM);
    sim_topk<<<dim3(B / 128, NSLICE), 256, SMEM>>>(N, Ntiles);

    merge_out<<<(B * 32 + 255) / 256, 256>>>(memory, out, N, B);
}